// round 3
// baseline (speedup 1.0000x reference)
#include <cuda_runtime.h>
#include <math.h>
#include <stdint.h>

#define NTASK 16
#define NEMB  25
#define DIM   512
#define HID   1024
#define NTRIP 2000
#define NCPT  64
#define M_ALL (NTASK*NEMB)   // 400
#define GCOLS (3*HID)        // 3072

// ---------------- scratch ----------------
__device__ float    g_G[M_ALL*GCOLS];
__device__ unsigned g_trip[NTASK*NTRIP];   // sorted, packed (a | p<<5 | n<<10)
__device__ int      g_cnt[NTASK];
__device__ float    g_q[NTASK*HID];
__device__ float    g_pooled[NTASK*DIM];
__device__ float    g_t1[NTASK*HID];
__device__ float    g_t2[NTASK*DIM];

__device__ __forceinline__ float warp_sum(float v) {
    #pragma unroll
    for (int o = 16; o > 0; o >>= 1) v += __shfl_xor_sync(0xffffffffu, v, o);
    return v;
}

// ---------------- K1: mining, smem-staged + ordered compaction ----------------
__global__ __launch_bounds__(256) void mask_kernel(const float* __restrict__ X,
                                                   unsigned* __restrict__ trip,
                                                   int* __restrict__ cnt) {
    extern __shared__ float xs[];            // [25][512] = 51.2 KB dynamic
    __shared__ float invn[NEMB], sqv[NEMB];
    __shared__ float D[NEMB][NEMB];
    __shared__ int wcnt[8];
    __shared__ int base_sh;
    int k = blockIdx.x;
    int tid = threadIdx.x, wid = tid >> 5, lane = tid & 31;

    // stage task embeddings
    const float4* xb4 = reinterpret_cast<const float4*>(X + (size_t)k * NEMB * DIM);
    float4* xs4 = reinterpret_cast<float4*>(xs);
    for (int i = tid; i < NEMB * (DIM/4); i += 256) xs4[i] = xb4[i];
    __syncthreads();

    // norms
    for (int r = wid; r < NEMB; r += 8) {
        float s = 0.f;
        for (int d = lane; d < DIM; d += 32) { float v = xs[r*DIM + d]; s += v*v; }
        s = warp_sum(s);
        if (lane == 0) invn[r] = rsqrtf(s);
    }
    __syncthreads();
    // normalize in place
    for (int i = tid; i < NEMB*DIM; i += 256) xs[i] *= invn[i >> 9];
    __syncthreads();
    // sq of normalized rows (matches reference formula order)
    for (int r = wid; r < NEMB; r += 8) {
        float s = 0.f;
        for (int d = lane; d < DIM; d += 32) { float v = xs[r*DIM + d]; s += v*v; }
        s = warp_sum(s);
        if (lane == 0) sqv[r] = s;
    }
    __syncthreads();
    // 300 pairwise distances from smem
    for (int p = wid; p < 300; p += 8) {
        int i = 0, rem = p;
        while (rem >= 24 - i) { rem -= 24 - i; i++; }
        int j = i + 1 + rem;
        float s = 0.f;
        for (int c = lane; c < DIM/4; c += 32) {
            float4 a = xs4[i*(DIM/4) + c];
            float4 b = xs4[j*(DIM/4) + c];
            s += a.x*b.x + a.y*b.y + a.z*b.z + a.w*b.w;
        }
        s = warp_sum(s);
        if (lane == 0) {
            float d2 = sqv[i] + sqv[j] - 2.f*s;
            float dd = sqrtf(fmaxf(d2, 0.f));
            D[i][j] = dd; D[j][i] = dd;
        }
    }
    __syncthreads();

    // ordered compaction (preserves t-order => sorted by a, then p, then n)
    if (tid == 0) base_sh = 0;
    __syncthreads();
    for (int rnd = 0; rnd < 8; rnd++) {
        int t = rnd*256 + tid;
        bool f = false; unsigned pack = 0;
        if (t < NTRIP) {
            int a  = t / 80;
            int rm = t - a*80;
            int pi = rm / 20, ni = rm - (rm/20)*20;
            int lbl = a % 5, ga = a / 5;
            int pg = pi + (pi >= ga ? 1 : 0);
            int p  = lbl + 5*pg;
            int m  = ni >> 2, w = ni & 3;
            int wn = w + (w >= lbl ? 1 : 0);
            int n  = 5*m + wn;
            float tm = D[a][n] - D[a][p];
            f = (tm > 0.f && tm <= 0.8f);
            pack = (unsigned)(a | (p << 5) | (n << 10));
        }
        unsigned bal = __ballot_sync(0xffffffffu, f);
        if (lane == 0) wcnt[wid] = __popc(bal);
        __syncthreads();
        int off = base_sh;
        #pragma unroll
        for (int w8 = 0; w8 < 8; w8++) if (w8 < wid) off += wcnt[w8];
        off += __popc(bal & ((1u << lane) - 1u));
        if (f) trip[k*NTRIP + off] = pack;
        __syncthreads();
        if (tid == 0) {
            int s = 0;
            #pragma unroll
            for (int w8 = 0; w8 < 8; w8++) s += wcnt[w8];
            base_sh += s;
        }
        __syncthreads();
    }
    if (tid == 0) cnt[k] = base_sh;
}

// ---------------- K2: tf32 mma GEMM, BM=64 BN=192 BK=16, one wave (112 blocks) --
__device__ __forceinline__ uint32_t tf32r(float f) {
    uint32_t r;
    asm("cvt.rna.tf32.f32 %0, %1;" : "=r"(r) : "f"(f));
    return r;
}

__global__ __launch_bounds__(256) void gemm1_tf32(const float* __restrict__ X,
                                                  const float* __restrict__ W1,
                                                  float* __restrict__ G) {
    __shared__ uint32_t As[16][72];
    __shared__ uint32_t Bs[16][200];
    int tid = threadIdx.x;
    int m0 = blockIdx.y * 64;
    int n0 = blockIdx.x * 192;
    int w = tid >> 5, lane = tid & 31;
    int wm = w & 1, wn = w >> 1;           // 2 x 4 warps, warp tile 32x48
    int grp = lane >> 2, tid4 = lane & 3;

    float c[2][6][4];
    #pragma unroll
    for (int mt = 0; mt < 2; mt++)
        #pragma unroll
        for (int nt = 0; nt < 6; nt++)
            #pragma unroll
            for (int r = 0; r < 4; r++) c[mt][nt][r] = 0.f;

    int lam = tid >> 2, lak = (tid & 3) << 2;
    int lbr = tid >> 4, lbc = (tid & 15) << 2;

    // per-chunk B pointers (columns may straddle the three W1 sections)
    const float* bptr[3];
    #pragma unroll
    for (int c3 = 0; c3 < 3; c3++) {
        int gc = n0 + lbc + c3*64;
        int s  = gc >> 10;
        int j  = gc & 1023;
        bptr[c3] = W1 + ((size_t)(s << 9)) * 1024 + j;
    }

    for (int k0 = 0; k0 < DIM; k0 += 16) {
        {
            int gm = m0 + lam;
            float4 v = make_float4(0.f, 0.f, 0.f, 0.f);
            if (gm < M_ALL) v = *reinterpret_cast<const float4*>(&X[(size_t)gm*DIM + k0 + lak]);
            As[lak+0][lam] = tf32r(v.x);
            As[lak+1][lam] = tf32r(v.y);
            As[lak+2][lam] = tf32r(v.z);
            As[lak+3][lam] = tf32r(v.w);
        }
        #pragma unroll
        for (int c3 = 0; c3 < 3; c3++) {
            float4 v = *reinterpret_cast<const float4*>(bptr[c3] + (size_t)(k0 + lbr) * 1024);
            int bc = lbc + c3*64;
            Bs[lbr][bc+0] = tf32r(v.x);
            Bs[lbr][bc+1] = tf32r(v.y);
            Bs[lbr][bc+2] = tf32r(v.z);
            Bs[lbr][bc+3] = tf32r(v.w);
        }
        __syncthreads();
        #pragma unroll
        for (int ks = 0; ks < 16; ks += 8) {
            uint32_t a[2][4], b[6][2];
            #pragma unroll
            for (int mt = 0; mt < 2; mt++) {
                int mr = wm*32 + mt*16 + grp;
                a[mt][0] = As[ks + tid4][mr];
                a[mt][1] = As[ks + tid4][mr + 8];
                a[mt][2] = As[ks + tid4 + 4][mr];
                a[mt][3] = As[ks + tid4 + 4][mr + 8];
            }
            #pragma unroll
            for (int nt = 0; nt < 6; nt++) {
                int nc = wn*48 + nt*8 + grp;
                b[nt][0] = Bs[ks + tid4][nc];
                b[nt][1] = Bs[ks + tid4 + 4][nc];
            }
            #pragma unroll
            for (int mt = 0; mt < 2; mt++)
                #pragma unroll
                for (int nt = 0; nt < 6; nt++) {
                    asm volatile(
                        "mma.sync.aligned.m16n8k8.row.col.f32.tf32.tf32.f32 "
                        "{%0,%1,%2,%3}, {%4,%5,%6,%7}, {%8,%9}, {%0,%1,%2,%3};"
                        : "+f"(c[mt][nt][0]), "+f"(c[mt][nt][1]),
                          "+f"(c[mt][nt][2]), "+f"(c[mt][nt][3])
                        : "r"(a[mt][0]), "r"(a[mt][1]), "r"(a[mt][2]), "r"(a[mt][3]),
                          "r"(b[nt][0]), "r"(b[nt][1]));
                }
        }
        __syncthreads();
    }
    #pragma unroll
    for (int mt = 0; mt < 2; mt++) {
        int r0 = m0 + wm*32 + mt*16 + grp;
        int r1 = r0 + 8;
        #pragma unroll
        for (int nt = 0; nt < 6; nt++) {
            int col = n0 + wn*48 + nt*8 + 2*tid4;
            if (r0 < M_ALL) {
                G[(size_t)r0*GCOLS + col]     = c[mt][nt][0];
                G[(size_t)r0*GCOLS + col + 1] = c[mt][nt][1];
            }
            if (r1 < M_ALL) {
                G[(size_t)r1*GCOLS + col]     = c[mt][nt][2];
                G[(size_t)r1*GCOLS + col + 1] = c[mt][nt][3];
            }
        }
    }
}

// ---------------- K3: pool with sorted-triplet register caching ----------------
__global__ __launch_bounds__(512) void pool_kernel(const float* __restrict__ G,
                                                   const float* __restrict__ b1,
                                                   const unsigned* __restrict__ trip,
                                                   const int* __restrict__ cnt,
                                                   float* __restrict__ q) {
    int cb = blockIdx.x;   // 8 chunks of 128 cols
    int k  = blockIdx.y;
    __shared__ float4 sG[75][32];
    __shared__ float4 red[16][32];
    int tid = threadIdx.x, w = tid >> 5, lane = tid & 31;
    const float* Gt = G + (size_t)k * NEMB * GCOLS;
    for (int idx = tid; idx < 75*32; idx += 512) {
        int c = idx & 31, row = idx >> 5;
        int s = row / NEMB, i = row - s*NEMB;
        sG[row][c] = *reinterpret_cast<const float4*>(
            &Gt[(size_t)i*GCOLS + (s << 10) + (cb << 7) + (c << 2)]);
    }
    __syncthreads();
    float4 b1v = *reinterpret_cast<const float4*>(&b1[(cb << 7) + (lane << 2)]);
    int n = cnt[k];
    const unsigned* tp = trip + k*NTRIP;
    // contiguous range per warp keeps (a,p) grouping from the sorted list
    int lo = (w * n) >> 4;
    int hi = ((w + 1) * n) >> 4;
    float4 acc = make_float4(0.f, 0.f, 0.f, 0.f);
    int cur_a = -1, cur_p = -1;
    float4 fa = acc, fap = acc;
    for (int t = lo; t < hi; t++) {
        unsigned u = __ldg(&tp[t]);                 // uniform across warp
        int a = u & 31, p = (u >> 5) & 31, nn = (u >> 10) & 31;
        if (a != cur_a) {
            float4 g = sG[a][lane];
            fa.x = g.x + b1v.x; fa.y = g.y + b1v.y;
            fa.z = g.z + b1v.z; fa.w = g.w + b1v.w;
            cur_a = a; cur_p = -1;
        }
        if (p != cur_p) {
            float4 g = sG[25 + p][lane];
            fap.x = fa.x + g.x; fap.y = fa.y + g.y;
            fap.z = fa.z + g.z; fap.w = fa.w + g.w;
            cur_p = p;
        }
        float4 gn = sG[50 + nn][lane];
        acc.x += fmaxf(fap.x + gn.x, 0.f);
        acc.y += fmaxf(fap.y + gn.y, 0.f);
        acc.z += fmaxf(fap.z + gn.z, 0.f);
        acc.w += fmaxf(fap.w + gn.w, 0.f);
    }
    red[w][lane] = acc;
    __syncthreads();
    if (tid < 32) {
        float4 s = red[0][tid];
        #pragma unroll
        for (int g = 1; g < 16; g++) {
            float4 r = red[g][tid];
            s.x += r.x; s.y += r.y; s.z += r.z; s.w += r.w;
        }
        *reinterpret_cast<float4*>(&q[k*HID + (cb << 7) + (tid << 2)]) = s;
    }
}

// ---------------- head GEMMs: full-K, 2 tasks per block, no atomics ----------
// mode 0: f=identity | mode 1: f = v + cnt[k]*bvec[i] | mode 2: f = relu(v + bvec[i])
__global__ __launch_bounds__(128) void head_kernel(const float* __restrict__ in,
                                                   const float* __restrict__ W,
                                                   const float* __restrict__ bvec,
                                                   const int* __restrict__ cnt,
                                                   float* __restrict__ out,
                                                   int Nin, int Nout, int mode) {
    int jb = blockIdx.x, kb = blockIdx.y * 2;
    __shared__ float s0[1024], s1[1024];
    int tid = threadIdx.x;
    for (int i = tid; i < Nin; i += 128) {
        float v0 = in[kb*Nin + i];
        float v1 = in[(kb+1)*Nin + i];
        if (mode == 1) {
            float b = bvec[i];
            v0 += (float)cnt[kb] * b;
            v1 += (float)cnt[kb+1] * b;
        } else if (mode == 2) {
            float b = bvec[i];
            v0 = fmaxf(v0 + b, 0.f);
            v1 = fmaxf(v1 + b, 0.f);
        }
        s0[i] = v0; s1[i] = v1;
    }
    __syncthreads();
    int j = jb*128 + tid;
    float a0 = 0.f, a1 = 0.f;
    #pragma unroll 4
    for (int i = 0; i < Nin; i++) {
        float wv = W[(size_t)i*Nout + j];
        a0 += s0[i]*wv;
        a1 += s1[i]*wv;
    }
    out[kb*Nout + j]     = a0;
    out[(kb+1)*Nout + j] = a1;
}

// ---------------- final: score = (t2+b4)@Wc + bc, softmax ----------------
__global__ __launch_bounds__(256) void final_kernel(const float* __restrict__ t2,
                                                    const float* __restrict__ b4,
                                                    const float* __restrict__ Wc,
                                                    const float* __restrict__ bc,
                                                    float* __restrict__ out) {
    int k = blockIdx.x;
    int tid = threadIdx.x, c = tid & 63, seg = tid >> 6;
    __shared__ float red[4][NCPT];
    __shared__ float sc[NCPT];
    float acc = 0.f;
    const float* tk = t2 + k*DIM;
    for (int i = seg*128; i < (seg+1)*128; i++)
        acc += (tk[i] + b4[i]) * Wc[i*NCPT + c];
    red[seg][c] = acc;
    __syncthreads();
    if (tid < NCPT)
        sc[c] = red[0][c] + red[1][c] + red[2][c] + red[3][c] + bc[c];
    __syncthreads();
    if (tid < NCPT) {
        float mx = -1e30f;
        #pragma unroll
        for (int i = 0; i < NCPT; i++) mx = fmaxf(mx, sc[i]);
        float sum = 0.f;
        #pragma unroll
        for (int i = 0; i < NCPT; i++) sum += expf(sc[i] - mx);
        out[k*NCPT + c] = expf(sc[c] - mx) / sum;
    }
}

// ---------------- launch ----------------
extern "C" void kernel_launch(void* const* d_in, const int* in_sizes, int n_in,
                              void* d_out, int out_size) {
    const float* X  = (const float*)d_in[0];
    const float* W1 = (const float*)d_in[1];
    const float* b1 = (const float*)d_in[2];
    const float* W2 = (const float*)d_in[3];
    const float* b2 = (const float*)d_in[4];
    const float* W3 = (const float*)d_in[5];
    const float* b3 = (const float*)d_in[6];
    const float* W4 = (const float*)d_in[7];
    const float* b4 = (const float*)d_in[8];
    const float* Wc = (const float*)d_in[9];
    const float* bc = (const float*)d_in[10];
    float* out = (float*)d_out;

    float *G, *q, *pooled, *t1, *t2; unsigned* trip; int* cnt;
    cudaGetSymbolAddress((void**)&G,      g_G);
    cudaGetSymbolAddress((void**)&trip,   g_trip);
    cudaGetSymbolAddress((void**)&cnt,    g_cnt);
    cudaGetSymbolAddress((void**)&q,      g_q);
    cudaGetSymbolAddress((void**)&pooled, g_pooled);
    cudaGetSymbolAddress((void**)&t1,     g_t1);
    cudaGetSymbolAddress((void**)&t2,     g_t2);

    const int mask_smem = NEMB * DIM * sizeof(float);   // 51.2 KB
    cudaFuncSetAttribute(mask_kernel, cudaFuncAttributeMaxDynamicSharedMemorySize, mask_smem);

    gemm1_tf32<<<dim3(GCOLS/192, (M_ALL + 63)/64), 256>>>(X, W1, G);
    mask_kernel<<<NTASK, 256, mask_smem>>>(X, trip, cnt);
    pool_kernel<<<dim3(8, NTASK), 512>>>(G, b1, trip, cnt, q);
    head_kernel<<<dim3(4, 8), 128>>>(q,      W2, nullptr, nullptr, pooled, HID, DIM, 0);
    head_kernel<<<dim3(8, 8), 128>>>(pooled, W3, b2,      cnt,     t1,     DIM, HID, 1);
    head_kernel<<<dim3(4, 8), 128>>>(t1,     W4, b3,      nullptr, t2,     HID, DIM, 2);
    final_kernel<<<NTASK, 256>>>(t2, b4, Wc, bc, out);
}

// round 4
// speedup vs baseline: 2.1770x; 2.1770x over previous
#include <cuda_runtime.h>
#include <math.h>
#include <stdint.h>

#define NTASK 16
#define NEMB  25
#define DIM   512
#define HID   1024
#define NTRIP 2000
#define NCPT  64
#define M_ALL (NTASK*NEMB)   // 400
#define GCOLS (3*HID)        // 3072

// ---------------- scratch ----------------
__device__ float    g_G[M_ALL*GCOLS];
__device__ unsigned g_trip[NTASK*NTRIP];   // sorted, packed (a | p<<5 | n<<10)
__device__ int      g_cnt[NTASK];
__device__ float    g_q[NTASK*HID];
__device__ float    g_pooled[NTASK*DIM];
__device__ float    g_t1[NTASK*HID];
__device__ float    g_t2[NTASK*DIM];

__device__ __forceinline__ float warp_sum(float v) {
    #pragma unroll
    for (int o = 16; o > 0; o >>= 1) v += __shfl_xor_sync(0xffffffffu, v, o);
    return v;
}

// ---------------- K1: mining, smem-staged + ordered compaction ----------------
__global__ __launch_bounds__(256) void mask_kernel(const float* __restrict__ X,
                                                   unsigned* __restrict__ trip,
                                                   int* __restrict__ cnt) {
    extern __shared__ float xs[];            // [25][512] = 51.2 KB dynamic
    __shared__ float invn[NEMB], sqv[NEMB];
    __shared__ float D[NEMB][NEMB];
    __shared__ int wcnt[8];
    __shared__ int base_sh;
    int k = blockIdx.x;
    int tid = threadIdx.x, wid = tid >> 5, lane = tid & 31;

    const float4* xb4 = reinterpret_cast<const float4*>(X + (size_t)k * NEMB * DIM);
    float4* xs4 = reinterpret_cast<float4*>(xs);
    for (int i = tid; i < NEMB * (DIM/4); i += 256) xs4[i] = xb4[i];
    __syncthreads();

    for (int r = wid; r < NEMB; r += 8) {
        float s = 0.f;
        for (int d = lane; d < DIM; d += 32) { float v = xs[r*DIM + d]; s += v*v; }
        s = warp_sum(s);
        if (lane == 0) invn[r] = rsqrtf(s);
    }
    __syncthreads();
    for (int i = tid; i < NEMB*DIM; i += 256) xs[i] *= invn[i >> 9];
    __syncthreads();
    for (int r = wid; r < NEMB; r += 8) {
        float s = 0.f;
        for (int d = lane; d < DIM; d += 32) { float v = xs[r*DIM + d]; s += v*v; }
        s = warp_sum(s);
        if (lane == 0) sqv[r] = s;
    }
    __syncthreads();
    for (int p = wid; p < 300; p += 8) {
        int i = 0, rem = p;
        while (rem >= 24 - i) { rem -= 24 - i; i++; }
        int j = i + 1 + rem;
        float s = 0.f;
        for (int c = lane; c < DIM/4; c += 32) {
            float4 a = xs4[i*(DIM/4) + c];
            float4 b = xs4[j*(DIM/4) + c];
            s += a.x*b.x + a.y*b.y + a.z*b.z + a.w*b.w;
        }
        s = warp_sum(s);
        if (lane == 0) {
            float d2 = sqv[i] + sqv[j] - 2.f*s;
            float dd = sqrtf(fmaxf(d2, 0.f));
            D[i][j] = dd; D[j][i] = dd;
        }
    }
    __syncthreads();

    if (tid == 0) base_sh = 0;
    __syncthreads();
    for (int rnd = 0; rnd < 8; rnd++) {
        int t = rnd*256 + tid;
        bool f = false; unsigned pack = 0;
        if (t < NTRIP) {
            int a  = t / 80;
            int rm = t - a*80;
            int pi = rm / 20, ni = rm - (rm/20)*20;
            int lbl = a % 5, ga = a / 5;
            int pg = pi + (pi >= ga ? 1 : 0);
            int p  = lbl + 5*pg;
            int m  = ni >> 2, w = ni & 3;
            int wn = w + (w >= lbl ? 1 : 0);
            int n  = 5*m + wn;
            float tm = D[a][n] - D[a][p];
            f = (tm > 0.f && tm <= 0.8f);
            pack = (unsigned)(a | (p << 5) | (n << 10));
        }
        unsigned bal = __ballot_sync(0xffffffffu, f);
        if (lane == 0) wcnt[wid] = __popc(bal);
        __syncthreads();
        int off = base_sh;
        #pragma unroll
        for (int w8 = 0; w8 < 8; w8++) if (w8 < wid) off += wcnt[w8];
        off += __popc(bal & ((1u << lane) - 1u));
        if (f) trip[k*NTRIP + off] = pack;
        __syncthreads();
        if (tid == 0) {
            int s = 0;
            #pragma unroll
            for (int w8 = 0; w8 < 8; w8++) s += wcnt[w8];
            base_sh += s;
        }
        __syncthreads();
    }
    if (tid == 0) cnt[k] = base_sh;
}

// ---------------- K2: tf32 mma GEMM, BM=64 BN=192 BK=16 ----------------
__device__ __forceinline__ uint32_t tf32r(float f) {
    uint32_t r;
    asm("cvt.rna.tf32.f32 %0, %1;" : "=r"(r) : "f"(f));
    return r;
}

__global__ __launch_bounds__(256) void gemm1_tf32(const float* __restrict__ X,
                                                  const float* __restrict__ W1,
                                                  float* __restrict__ G) {
    __shared__ uint32_t As[16][72];
    __shared__ uint32_t Bs[16][200];
    int tid = threadIdx.x;
    int m0 = blockIdx.y * 64;
    int n0 = blockIdx.x * 192;
    int w = tid >> 5, lane = tid & 31;
    int wm = w & 1, wn = w >> 1;
    int grp = lane >> 2, tid4 = lane & 3;

    float c[2][6][4];
    #pragma unroll
    for (int mt = 0; mt < 2; mt++)
        #pragma unroll
        for (int nt = 0; nt < 6; nt++)
            #pragma unroll
            for (int r = 0; r < 4; r++) c[mt][nt][r] = 0.f;

    int lam = tid >> 2, lak = (tid & 3) << 2;
    int lbr = tid >> 4, lbc = (tid & 15) << 2;

    const float* bptr[3];
    #pragma unroll
    for (int c3 = 0; c3 < 3; c3++) {
        int gc = n0 + lbc + c3*64;
        int s  = gc >> 10;
        int j  = gc & 1023;
        bptr[c3] = W1 + ((size_t)(s << 9)) * 1024 + j;
    }

    for (int k0 = 0; k0 < DIM; k0 += 16) {
        {
            int gm = m0 + lam;
            float4 v = make_float4(0.f, 0.f, 0.f, 0.f);
            if (gm < M_ALL) v = *reinterpret_cast<const float4*>(&X[(size_t)gm*DIM + k0 + lak]);
            As[lak+0][lam] = tf32r(v.x);
            As[lak+1][lam] = tf32r(v.y);
            As[lak+2][lam] = tf32r(v.z);
            As[lak+3][lam] = tf32r(v.w);
        }
        #pragma unroll
        for (int c3 = 0; c3 < 3; c3++) {
            float4 v = *reinterpret_cast<const float4*>(bptr[c3] + (size_t)(k0 + lbr) * 1024);
            int bc = lbc + c3*64;
            Bs[lbr][bc+0] = tf32r(v.x);
            Bs[lbr][bc+1] = tf32r(v.y);
            Bs[lbr][bc+2] = tf32r(v.z);
            Bs[lbr][bc+3] = tf32r(v.w);
        }
        __syncthreads();
        #pragma unroll
        for (int ks = 0; ks < 16; ks += 8) {
            uint32_t a[2][4], b[6][2];
            #pragma unroll
            for (int mt = 0; mt < 2; mt++) {
                int mr = wm*32 + mt*16 + grp;
                a[mt][0] = As[ks + tid4][mr];
                a[mt][1] = As[ks + tid4][mr + 8];
                a[mt][2] = As[ks + tid4 + 4][mr];
                a[mt][3] = As[ks + tid4 + 4][mr + 8];
            }
            #pragma unroll
            for (int nt = 0; nt < 6; nt++) {
                int nc = wn*48 + nt*8 + grp;
                b[nt][0] = Bs[ks + tid4][nc];
                b[nt][1] = Bs[ks + tid4 + 4][nc];
            }
            #pragma unroll
            for (int mt = 0; mt < 2; mt++)
                #pragma unroll
                for (int nt = 0; nt < 6; nt++) {
                    asm volatile(
                        "mma.sync.aligned.m16n8k8.row.col.f32.tf32.tf32.f32 "
                        "{%0,%1,%2,%3}, {%4,%5,%6,%7}, {%8,%9}, {%0,%1,%2,%3};"
                        : "+f"(c[mt][nt][0]), "+f"(c[mt][nt][1]),
                          "+f"(c[mt][nt][2]), "+f"(c[mt][nt][3])
                        : "r"(a[mt][0]), "r"(a[mt][1]), "r"(a[mt][2]), "r"(a[mt][3]),
                          "r"(b[nt][0]), "r"(b[nt][1]));
                }
        }
        __syncthreads();
    }
    #pragma unroll
    for (int mt = 0; mt < 2; mt++) {
        int r0 = m0 + wm*32 + mt*16 + grp;
        int r1 = r0 + 8;
        #pragma unroll
        for (int nt = 0; nt < 6; nt++) {
            int col = n0 + wn*48 + nt*8 + 2*tid4;
            if (r0 < M_ALL) {
                G[(size_t)r0*GCOLS + col]     = c[mt][nt][0];
                G[(size_t)r0*GCOLS + col + 1] = c[mt][nt][1];
            }
            if (r1 < M_ALL) {
                G[(size_t)r1*GCOLS + col]     = c[mt][nt][2];
                G[(size_t)r1*GCOLS + col + 1] = c[mt][nt][3];
            }
        }
    }
}

// ---------------- K3: pool with sorted-triplet register caching ----------------
__global__ __launch_bounds__(512) void pool_kernel(const float* __restrict__ G,
                                                   const float* __restrict__ b1,
                                                   const unsigned* __restrict__ trip,
                                                   const int* __restrict__ cnt,
                                                   float* __restrict__ q) {
    int cb = blockIdx.x;
    int k  = blockIdx.y;
    __shared__ float4 sG[75][32];
    __shared__ float4 red[16][32];
    int tid = threadIdx.x, w = tid >> 5, lane = tid & 31;
    const float* Gt = G + (size_t)k * NEMB * GCOLS;
    for (int idx = tid; idx < 75*32; idx += 512) {
        int c = idx & 31, row = idx >> 5;
        int s = row / NEMB, i = row - s*NEMB;
        sG[row][c] = *reinterpret_cast<const float4*>(
            &Gt[(size_t)i*GCOLS + (s << 10) + (cb << 7) + (c << 2)]);
    }
    __syncthreads();
    float4 b1v = *reinterpret_cast<const float4*>(&b1[(cb << 7) + (lane << 2)]);
    int n = cnt[k];
    const unsigned* tp = trip + k*NTRIP;
    int lo = (w * n) >> 4;
    int hi = ((w + 1) * n) >> 4;
    float4 acc = make_float4(0.f, 0.f, 0.f, 0.f);
    int cur_a = -1, cur_p = -1;
    float4 fa = acc, fap = acc;
    for (int t = lo; t < hi; t++) {
        unsigned u = __ldg(&tp[t]);
        int a = u & 31, p = (u >> 5) & 31, nn = (u >> 10) & 31;
        if (a != cur_a) {
            float4 g = sG[a][lane];
            fa.x = g.x + b1v.x; fa.y = g.y + b1v.y;
            fa.z = g.z + b1v.z; fa.w = g.w + b1v.w;
            cur_a = a; cur_p = -1;
        }
        if (p != cur_p) {
            float4 g = sG[25 + p][lane];
            fap.x = fa.x + g.x; fap.y = fa.y + g.y;
            fap.z = fa.z + g.z; fap.w = fa.w + g.w;
            cur_p = p;
        }
        float4 gn = sG[50 + nn][lane];
        acc.x += fmaxf(fap.x + gn.x, 0.f);
        acc.y += fmaxf(fap.y + gn.y, 0.f);
        acc.z += fmaxf(fap.z + gn.z, 0.f);
        acc.w += fmaxf(fap.w + gn.w, 0.f);
    }
    red[w][lane] = acc;
    __syncthreads();
    if (tid < 32) {
        float4 s = red[0][tid];
        #pragma unroll
        for (int g = 1; g < 16; g++) {
            float4 r = red[g][tid];
            s.x += r.x; s.y += r.y; s.z += r.z; s.w += r.w;
        }
        *reinterpret_cast<float4*>(&q[k*HID + (cb << 7) + (tid << 2)]) = s;
    }
}

// ---------------- zero-init ----------------
__global__ void zero3_kernel(float* a, int na, float* b, int nb, float* c, int nc) {
    int i = blockIdx.x*blockDim.x + threadIdx.x;
    int st = gridDim.x*blockDim.x;
    for (int t = i; t < na; t += st) a[t] = 0.f;
    for (int t = i; t < nb; t += st) b[t] = 0.f;
    for (int t = i; t < nc; t += st) c[t] = 0.f;
}

// ---------------- head GEMMs: split-K 64, 128 blocks, atomic accumulate ------
// out[16,Nout] += f(in)[16,Nin] @ W ; grid (Nout/64, Nin/64), 256 threads
// mode 0: f=v | mode 1: f=v+cnt[t]*bvec[i] | mode 2: f=relu(v+bvec[i])
__global__ __launch_bounds__(256) void head_kernel(const float* __restrict__ in,
                                                   const float* __restrict__ W,
                                                   const float* __restrict__ bvec,
                                                   const int* __restrict__ cnt,
                                                   float* __restrict__ out,
                                                   int Nin, int Nout, int mode) {
    __shared__ float sf[64][16];   // [i_local][task]
    int tid = threadIdx.x;
    int jb = blockIdx.x * 64, kb = blockIdx.y * 64;
    // stage f(in): 1024 values
    for (int idx = tid; idx < 1024; idx += 256) {
        int il = idx >> 4, t = idx & 15;
        float v = in[t*Nin + kb + il];
        if (mode == 1)      v += (float)cnt[t] * bvec[kb + il];
        else if (mode == 2) v  = fmaxf(v + bvec[kb + il], 0.f);
        sf[il][t] = v;
    }
    __syncthreads();
    int j  = jb + (tid & 63);
    int kh = tid >> 6;              // 4 groups x 16 K each
    float acc[16];
    #pragma unroll
    for (int t = 0; t < 16; t++) acc[t] = 0.f;
    const float4* sf4 = reinterpret_cast<const float4*>(sf);
    #pragma unroll
    for (int ii = 0; ii < 16; ii++) {
        int i = (kh << 4) + ii;
        float wv = __ldg(&W[(size_t)(kb + i)*Nout + j]);
        float4 f0 = sf4[i*4 + 0];
        float4 f1 = sf4[i*4 + 1];
        float4 f2 = sf4[i*4 + 2];
        float4 f3 = sf4[i*4 + 3];
        acc[0]  += f0.x*wv; acc[1]  += f0.y*wv; acc[2]  += f0.z*wv; acc[3]  += f0.w*wv;
        acc[4]  += f1.x*wv; acc[5]  += f1.y*wv; acc[6]  += f1.z*wv; acc[7]  += f1.w*wv;
        acc[8]  += f2.x*wv; acc[9]  += f2.y*wv; acc[10] += f2.z*wv; acc[11] += f2.w*wv;
        acc[12] += f3.x*wv; acc[13] += f3.y*wv; acc[14] += f3.z*wv; acc[15] += f3.w*wv;
    }
    #pragma unroll
    for (int t = 0; t < 16; t++)
        atomicAdd(&out[t*Nout + j], acc[t]);
}

// ---------------- final: score = (t2+b4)@Wc + bc, softmax ----------------
__global__ __launch_bounds__(256) void final_kernel(const float* __restrict__ t2,
                                                    const float* __restrict__ b4,
                                                    const float* __restrict__ Wc,
                                                    const float* __restrict__ bc,
                                                    float* __restrict__ out) {
    int k = blockIdx.x;
    int tid = threadIdx.x, c = tid & 63, seg = tid >> 6;
    __shared__ float red[4][NCPT];
    __shared__ float sc[NCPT];
    float acc = 0.f;
    const float* tk = t2 + k*DIM;
    for (int i = seg*128; i < (seg+1)*128; i++)
        acc += (tk[i] + b4[i]) * Wc[i*NCPT + c];
    red[seg][c] = acc;
    __syncthreads();
    if (tid < NCPT)
        sc[c] = red[0][c] + red[1][c] + red[2][c] + red[3][c] + bc[c];
    __syncthreads();
    if (tid < NCPT) {
        float mx = -1e30f;
        #pragma unroll
        for (int i = 0; i < NCPT; i++) mx = fmaxf(mx, sc[i]);
        float sum = 0.f;
        #pragma unroll
        for (int i = 0; i < NCPT; i++) sum += expf(sc[i] - mx);
        out[k*NCPT + c] = expf(sc[c] - mx) / sum;
    }
}

// ---------------- launch ----------------
extern "C" void kernel_launch(void* const* d_in, const int* in_sizes, int n_in,
                              void* d_out, int out_size) {
    const float* X  = (const float*)d_in[0];
    const float* W1 = (const float*)d_in[1];
    const float* b1 = (const float*)d_in[2];
    const float* W2 = (const float*)d_in[3];
    const float* b2 = (const float*)d_in[4];
    const float* W3 = (const float*)d_in[5];
    const float* b3 = (const float*)d_in[6];
    const float* W4 = (const float*)d_in[7];
    const float* b4 = (const float*)d_in[8];
    const float* Wc = (const float*)d_in[9];
    const float* bc = (const float*)d_in[10];
    float* out = (float*)d_out;

    float *G, *q, *pooled, *t1, *t2; unsigned* trip; int* cnt;
    cudaGetSymbolAddress((void**)&G,      g_G);
    cudaGetSymbolAddress((void**)&trip,   g_trip);
    cudaGetSymbolAddress((void**)&cnt,    g_cnt);
    cudaGetSymbolAddress((void**)&q,      g_q);
    cudaGetSymbolAddress((void**)&pooled, g_pooled);
    cudaGetSymbolAddress((void**)&t1,     g_t1);
    cudaGetSymbolAddress((void**)&t2,     g_t2);

    const int mask_smem = NEMB * DIM * sizeof(float);   // 51.2 KB
    cudaFuncSetAttribute(mask_kernel, cudaFuncAttributeMaxDynamicSharedMemorySize, mask_smem);

    zero3_kernel<<<64, 256>>>(pooled, NTASK*DIM, t1, NTASK*HID, t2, NTASK*DIM);
    gemm1_tf32<<<dim3(GCOLS/192, (M_ALL + 63)/64), 256>>>(X, W1, G);
    mask_kernel<<<NTASK, 256, mask_smem>>>(X, trip, cnt);
    pool_kernel<<<dim3(8, NTASK), 512>>>(G, b1, trip, cnt, q);
    head_kernel<<<dim3(DIM/64, HID/64), 256>>>(q,      W2, nullptr, nullptr, pooled, HID, DIM, 0);
    head_kernel<<<dim3(HID/64, DIM/64), 256>>>(pooled, W3, b2,      cnt,     t1,     DIM, HID, 1);
    head_kernel<<<dim3(DIM/64, HID/64), 256>>>(t1,     W4, b3,      nullptr, t2,     HID, DIM, 2);
    final_kernel<<<NTASK, 256>>>(t2, b4, Wc, bc, out);
}

// round 5
// speedup vs baseline: 2.9153x; 1.3392x over previous
#include <cuda_runtime.h>
#include <math.h>
#include <stdint.h>

#define NTASK 16
#define NEMB  25
#define DIM   512
#define HID   1024
#define NTRIP 2000
#define NCPT  64
#define M_ALL (NTASK*NEMB)   // 400
#define GCOLS (3*HID)        // 3072
#define NB2   128            // grid of mega kernel (<=148: one wave, barrier-safe)

// ---------------- scratch ----------------
__device__ float    g_G[M_ALL*GCOLS];
__device__ unsigned g_trip[NTASK*NTRIP];
__device__ int      g_cnt[NTASK];
__device__ float    g_q[NTASK*HID];
__device__ float    g_pooled[NTASK*DIM];
__device__ float    g_t1[NTASK*HID];
__device__ float    g_t2[NTASK*DIM];
// DIY grid barrier state (zero-initialized; cnt returns to 0 each run, gen monotonic)
__device__ unsigned g_bcnt[4];
__device__ unsigned g_bgen[4];

__device__ __forceinline__ float warp_sum(float v) {
    #pragma unroll
    for (int o = 16; o > 0; o >>= 1) v += __shfl_xor_sync(0xffffffffu, v, o);
    return v;
}

__device__ __forceinline__ uint32_t tf32r(float f) {
    uint32_t r;
    asm("cvt.rna.tf32.f32 %0, %1;" : "=r"(r) : "f"(f));
    return r;
}

// ---------------- generation-based grid barrier (grid <= one wave) ----------
__device__ __forceinline__ void grid_barrier(int s, unsigned nb) {
    __syncthreads();
    if (threadIdx.x == 0) {
        unsigned g0 = *((volatile unsigned*)&g_bgen[s]);   // pre-arrival generation
        __threadfence();                                    // release my writes
        unsigned old = atomicAdd(&g_bcnt[s], 1u);
        if (old == nb - 1u) {
            g_bcnt[s] = 0u;                                 // all arrived; safe to reset
            __threadfence();
            atomicAdd(&g_bgen[s], 1u);
        } else {
            while (*((volatile unsigned*)&g_bgen[s]) == g0) { }
            __threadfence();                                // acquire
        }
    }
    __syncthreads();
}

// ============================================================================
// L1: fused  [blocks 0..111] tf32 mma GEMM  |  [blocks 112..127] triplet mining
// ============================================================================
__global__ __launch_bounds__(256) void fused1_kernel(const float* __restrict__ X,
                                                     const float* __restrict__ W1,
                                                     float* __restrict__ G,
                                                     unsigned* __restrict__ trip,
                                                     int* __restrict__ cnt) {
    int bid = blockIdx.x;
    int tid = threadIdx.x;

    if (bid < 112) {
        // ------------------- GEMM part: BM=64, BN=192, BK=16 -------------------
        __shared__ uint32_t As[16][72];
        __shared__ uint32_t Bs[16][200];
        int m0 = (bid >> 4) * 64;
        int n0 = (bid & 15) * 192;
        int w = tid >> 5, lane = tid & 31;
        int wm = w & 1, wn = w >> 1;
        int grp = lane >> 2, tid4 = lane & 3;

        float c[2][6][4];
        #pragma unroll
        for (int mt = 0; mt < 2; mt++)
            #pragma unroll
            for (int nt = 0; nt < 6; nt++)
                #pragma unroll
                for (int r = 0; r < 4; r++) c[mt][nt][r] = 0.f;

        int lam = tid >> 2, lak = (tid & 3) << 2;
        int lbr = tid >> 4, lbc = (tid & 15) << 2;

        const float* bptr[3];
        #pragma unroll
        for (int c3 = 0; c3 < 3; c3++) {
            int gc = n0 + lbc + c3*64;
            int s  = gc >> 10;
            int j  = gc & 1023;
            bptr[c3] = W1 + ((size_t)(s << 9)) * 1024 + j;
        }

        for (int k0 = 0; k0 < DIM; k0 += 16) {
            {
                int gm = m0 + lam;
                float4 v = make_float4(0.f, 0.f, 0.f, 0.f);
                if (gm < M_ALL) v = *reinterpret_cast<const float4*>(&X[(size_t)gm*DIM + k0 + lak]);
                As[lak+0][lam] = tf32r(v.x);
                As[lak+1][lam] = tf32r(v.y);
                As[lak+2][lam] = tf32r(v.z);
                As[lak+3][lam] = tf32r(v.w);
            }
            #pragma unroll
            for (int c3 = 0; c3 < 3; c3++) {
                float4 v = *reinterpret_cast<const float4*>(bptr[c3] + (size_t)(k0 + lbr) * 1024);
                int bc = lbc + c3*64;
                Bs[lbr][bc+0] = tf32r(v.x);
                Bs[lbr][bc+1] = tf32r(v.y);
                Bs[lbr][bc+2] = tf32r(v.z);
                Bs[lbr][bc+3] = tf32r(v.w);
            }
            __syncthreads();
            #pragma unroll
            for (int ks = 0; ks < 16; ks += 8) {
                uint32_t a[2][4], b[6][2];
                #pragma unroll
                for (int mt = 0; mt < 2; mt++) {
                    int mr = wm*32 + mt*16 + grp;
                    a[mt][0] = As[ks + tid4][mr];
                    a[mt][1] = As[ks + tid4][mr + 8];
                    a[mt][2] = As[ks + tid4 + 4][mr];
                    a[mt][3] = As[ks + tid4 + 4][mr + 8];
                }
                #pragma unroll
                for (int nt = 0; nt < 6; nt++) {
                    int nc = wn*48 + nt*8 + grp;
                    b[nt][0] = Bs[ks + tid4][nc];
                    b[nt][1] = Bs[ks + tid4 + 4][nc];
                }
                #pragma unroll
                for (int mt = 0; mt < 2; mt++)
                    #pragma unroll
                    for (int nt = 0; nt < 6; nt++) {
                        asm volatile(
                            "mma.sync.aligned.m16n8k8.row.col.f32.tf32.tf32.f32 "
                            "{%0,%1,%2,%3}, {%4,%5,%6,%7}, {%8,%9}, {%0,%1,%2,%3};"
                            : "+f"(c[mt][nt][0]), "+f"(c[mt][nt][1]),
                              "+f"(c[mt][nt][2]), "+f"(c[mt][nt][3])
                            : "r"(a[mt][0]), "r"(a[mt][1]), "r"(a[mt][2]), "r"(a[mt][3]),
                              "r"(b[nt][0]), "r"(b[nt][1]));
                    }
            }
            __syncthreads();
        }
        #pragma unroll
        for (int mt = 0; mt < 2; mt++) {
            int r0 = m0 + wm*32 + mt*16 + grp;
            int r1 = r0 + 8;
            #pragma unroll
            for (int nt = 0; nt < 6; nt++) {
                int col = n0 + wn*48 + nt*8 + 2*tid4;
                if (r0 < M_ALL) {
                    G[(size_t)r0*GCOLS + col]     = c[mt][nt][0];
                    G[(size_t)r0*GCOLS + col + 1] = c[mt][nt][1];
                }
                if (r1 < M_ALL) {
                    G[(size_t)r1*GCOLS + col]     = c[mt][nt][2];
                    G[(size_t)r1*GCOLS + col + 1] = c[mt][nt][3];
                }
            }
        }
    } else {
        // ------------------- mining part (task = bid - 112) -------------------
        extern __shared__ float xs[];    // 25*512 floats = 51.2 KB
        __shared__ float invn[NEMB], sqv[NEMB];
        __shared__ float D[NEMB][NEMB];
        __shared__ int wcnt[8];
        __shared__ int base_sh;
        int k = bid - 112;
        int wid = tid >> 5, lane = tid & 31;

        const float4* xb4 = reinterpret_cast<const float4*>(X + (size_t)k * NEMB * DIM);
        float4* xs4 = reinterpret_cast<float4*>(xs);
        for (int i = tid; i < NEMB * (DIM/4); i += 256) xs4[i] = xb4[i];
        __syncthreads();

        for (int r = wid; r < NEMB; r += 8) {
            float s = 0.f;
            for (int d = lane; d < DIM; d += 32) { float v = xs[r*DIM + d]; s += v*v; }
            s = warp_sum(s);
            if (lane == 0) invn[r] = rsqrtf(s);
        }
        __syncthreads();
        for (int i = tid; i < NEMB*DIM; i += 256) xs[i] *= invn[i >> 9];
        __syncthreads();
        for (int r = wid; r < NEMB; r += 8) {
            float s = 0.f;
            for (int d = lane; d < DIM; d += 32) { float v = xs[r*DIM + d]; s += v*v; }
            s = warp_sum(s);
            if (lane == 0) sqv[r] = s;
        }
        __syncthreads();
        for (int p = wid; p < 300; p += 8) {
            int i = 0, rem = p;
            while (rem >= 24 - i) { rem -= 24 - i; i++; }
            int j = i + 1 + rem;
            float s = 0.f;
            for (int cc = lane; cc < DIM/4; cc += 32) {
                float4 a = xs4[i*(DIM/4) + cc];
                float4 b = xs4[j*(DIM/4) + cc];
                s += a.x*b.x + a.y*b.y + a.z*b.z + a.w*b.w;
            }
            s = warp_sum(s);
            if (lane == 0) {
                float d2 = sqv[i] + sqv[j] - 2.f*s;
                float dd = sqrtf(fmaxf(d2, 0.f));
                D[i][j] = dd; D[j][i] = dd;
            }
        }
        __syncthreads();

        if (tid == 0) base_sh = 0;
        __syncthreads();
        for (int rnd = 0; rnd < 8; rnd++) {
            int t = rnd*256 + tid;
            bool f = false; unsigned pack = 0;
            if (t < NTRIP) {
                int a  = t / 80;
                int rm = t - a*80;
                int pi = rm / 20, ni = rm - (rm/20)*20;
                int lbl = a % 5, ga = a / 5;
                int pg = pi + (pi >= ga ? 1 : 0);
                int p  = lbl + 5*pg;
                int m  = ni >> 2, w = ni & 3;
                int wn = w + (w >= lbl ? 1 : 0);
                int n  = 5*m + wn;
                float tm = D[a][n] - D[a][p];
                f = (tm > 0.f && tm <= 0.8f);
                pack = (unsigned)(a | (p << 5) | (n << 10));
            }
            unsigned bal = __ballot_sync(0xffffffffu, f);
            if (lane == 0) wcnt[wid] = __popc(bal);
            __syncthreads();
            int off = base_sh;
            #pragma unroll
            for (int w8 = 0; w8 < 8; w8++) if (w8 < wid) off += wcnt[w8];
            off += __popc(bal & ((1u << lane) - 1u));
            if (f) trip[k*NTRIP + off] = pack;
            __syncthreads();
            if (tid == 0) {
                int s = 0;
                #pragma unroll
                for (int w8 = 0; w8 < 8; w8++) s += wcnt[w8];
                base_sh += s;
            }
            __syncthreads();
        }
        if (tid == 0) cnt[k] = base_sh;
    }
}

// ============================================================================
// L2: mega kernel — pool -> head1 -> head2 -> head3 -> final, DIY grid barriers
// dynamic smem: sG (38400 B) | region B (8192 B: red / sf / fred+sc)
// ============================================================================
__device__ __forceinline__ void head_stage(const float* __restrict__ in,
                                           const float* __restrict__ W,
                                           const float* __restrict__ bvec,
                                           const int* __restrict__ cntp,
                                           float* __restrict__ outp,
                                           int Nin, int Nout, int mode,
                                           int jb, int kb,
                                           float (*sf)[16], int tid) {
    int kb64 = kb * 64;
    for (int idx = tid; idx < 1024; idx += 512) {
        int il = idx >> 4, t = idx & 15;
        float v = in[t*Nin + kb64 + il];
        if (mode == 1)      v += (float)cntp[t] * bvec[kb64 + il];
        else if (mode == 2) v  = fmaxf(v + bvec[kb64 + il], 0.f);
        sf[il][t] = v;
    }
    __syncthreads();
    int j  = jb*64 + (tid & 63);
    int kh = tid >> 6;               // 8 groups x 8 K rows
    float acc[16];
    #pragma unroll
    for (int t = 0; t < 16; t++) acc[t] = 0.f;
    const float4* sf4 = reinterpret_cast<const float4*>(sf);
    #pragma unroll
    for (int ii = 0; ii < 8; ii++) {
        int i = (kh << 3) + ii;
        float wv = __ldg(&W[(size_t)(kb64 + i)*Nout + j]);
        float4 f0 = sf4[i*4 + 0];
        float4 f1 = sf4[i*4 + 1];
        float4 f2 = sf4[i*4 + 2];
        float4 f3 = sf4[i*4 + 3];
        acc[0]  += f0.x*wv; acc[1]  += f0.y*wv; acc[2]  += f0.z*wv; acc[3]  += f0.w*wv;
        acc[4]  += f1.x*wv; acc[5]  += f1.y*wv; acc[6]  += f1.z*wv; acc[7]  += f1.w*wv;
        acc[8]  += f2.x*wv; acc[9]  += f2.y*wv; acc[10] += f2.z*wv; acc[11] += f2.w*wv;
        acc[12] += f3.x*wv; acc[13] += f3.y*wv; acc[14] += f3.z*wv; acc[15] += f3.w*wv;
    }
    #pragma unroll
    for (int t = 0; t < 16; t++)
        atomicAdd(&outp[t*Nout + j], acc[t]);
}

__global__ __launch_bounds__(512) void mega_kernel(const float* __restrict__ G,
                                                   const float* __restrict__ b1,
                                                   const unsigned* __restrict__ trip,
                                                   const int* __restrict__ cnt,
                                                   const float* __restrict__ W2,
                                                   const float* __restrict__ b2,
                                                   const float* __restrict__ W3,
                                                   const float* __restrict__ b3,
                                                   const float* __restrict__ W4,
                                                   const float* __restrict__ b4v,
                                                   const float* __restrict__ Wc,
                                                   const float* __restrict__ bc,
                                                   float* __restrict__ q,
                                                   float* __restrict__ pooled,
                                                   float* __restrict__ t1,
                                                   float* __restrict__ t2,
                                                   float* __restrict__ out) {
    extern __shared__ char smem2[];
    float4 (*sG)[32]  = reinterpret_cast<float4(*)[32]>(smem2);          // 75*32*16
    char* rb = smem2 + 75*32*16;
    float4 (*red)[32] = reinterpret_cast<float4(*)[32]>(rb);             // 16*32*16 (pool)
    float  (*sf)[16]  = reinterpret_cast<float(*)[16]>(rb);              // 64*16*4 (heads)
    float  (*fred)[64]= reinterpret_cast<float(*)[64]>(rb);              // 8*64*4 (final)
    float*  sc        = reinterpret_cast<float*>(rb + 8*64*4);           // 64*4

    int bid = blockIdx.x;
    int tid = threadIdx.x;
    unsigned nb = gridDim.x;

    // ---- zero atomic accumulators (ordered before head1 by barrier 0) ----
    {
        int gidx = bid*512 + tid;                 // 65536 threads total
        if (gidx < NTASK*DIM)  pooled[gidx] = 0.f;
        if (gidx < NTASK*HID)  t1[gidx]     = 0.f;
        if (gidx < NTASK*DIM)  t2[gidx]     = 0.f;
    }

    // ---- stage 0: pool (block = (task k, col-chunk cb)) ----
    {
        int cb = bid & 7, k = bid >> 3;
        int w = tid >> 5, lane = tid & 31;
        const float* Gt = G + (size_t)k * NEMB * GCOLS;
        for (int idx = tid; idx < 75*32; idx += 512) {
            int c = idx & 31, row = idx >> 5;
            int s = row / NEMB, i = row - s*NEMB;
            sG[row][c] = *reinterpret_cast<const float4*>(
                &Gt[(size_t)i*GCOLS + (s << 10) + (cb << 7) + (c << 2)]);
        }
        __syncthreads();
        float4 b1v = *reinterpret_cast<const float4*>(&b1[(cb << 7) + (lane << 2)]);
        int n = cnt[k];
        const unsigned* tp = trip + k*NTRIP;
        int lo = (w * n) >> 4;
        int hi = ((w + 1) * n) >> 4;
        float4 acc = make_float4(0.f, 0.f, 0.f, 0.f);
        int cur_a = -1, cur_p = -1;
        float4 fa = acc, fap = acc;
        for (int t = lo; t < hi; t++) {
            unsigned u = __ldg(&tp[t]);
            int a = u & 31, p = (u >> 5) & 31, nn = (u >> 10) & 31;
            if (a != cur_a) {
                float4 g = sG[a][lane];
                fa.x = g.x + b1v.x; fa.y = g.y + b1v.y;
                fa.z = g.z + b1v.z; fa.w = g.w + b1v.w;
                cur_a = a; cur_p = -1;
            }
            if (p != cur_p) {
                float4 g = sG[25 + p][lane];
                fap.x = fa.x + g.x; fap.y = fa.y + g.y;
                fap.z = fa.z + g.z; fap.w = fa.w + g.w;
                cur_p = p;
            }
            float4 gn = sG[50 + nn][lane];
            acc.x += fmaxf(fap.x + gn.x, 0.f);
            acc.y += fmaxf(fap.y + gn.y, 0.f);
            acc.z += fmaxf(fap.z + gn.z, 0.f);
            acc.w += fmaxf(fap.w + gn.w, 0.f);
        }
        red[w][lane] = acc;
        __syncthreads();
        if (tid < 32) {
            float4 s = red[0][tid];
            #pragma unroll
            for (int g = 1; g < 16; g++) {
                float4 r = red[g][tid];
                s.x += r.x; s.y += r.y; s.z += r.z; s.w += r.w;
            }
            *reinterpret_cast<float4*>(&q[k*HID + (cb << 7) + (tid << 2)]) = s;
        }
    }
    grid_barrier(0, nb);

    // ---- stage 1: pooled += q @ W2   (Nin=1024, Nout=512) ----
    head_stage(q, W2, nullptr, nullptr, pooled, HID, DIM, 0, bid & 7, bid >> 3, sf, tid);
    grid_barrier(1, nb);

    // ---- stage 2: t1 += (pooled + cnt*b2) @ W3   (Nin=512, Nout=1024) ----
    head_stage(pooled, W3, b2, cnt, t1, DIM, HID, 1, bid & 15, bid >> 4, sf, tid);
    grid_barrier(2, nb);

    // ---- stage 3: t2 += relu(t1 + b3) @ W4   (Nin=1024, Nout=512) ----
    head_stage(t1, W4, b3, nullptr, t2, HID, DIM, 2, bid & 7, bid >> 3, sf, tid);
    grid_barrier(3, nb);

    // ---- stage 4: final softmax (blocks 0..15) ----
    if (bid < NTASK) {
        int k = bid;
        int c = tid & 63, seg = tid >> 6;           // 8 segments x 64 rows
        float acc = 0.f;
        const float* tk = t2 + k*DIM;
        for (int i = seg*64; i < seg*64 + 64; i++)
            acc += (tk[i] + b4v[i]) * Wc[i*NCPT + c];
        fred[seg][c] = acc;
        __syncthreads();
        if (tid < NCPT) {
            float s = bc[c];
            #pragma unroll
            for (int g = 0; g < 8; g++) s += fred[g][c];
            sc[c] = s;
        }
        __syncthreads();
        if (tid < NCPT) {
            float v = sc[c];
            float mx = -1e30f;
            #pragma unroll
            for (int i = 0; i < NCPT; i++) mx = fmaxf(mx, sc[i]);
            float sum = 0.f;
            #pragma unroll
            for (int i = 0; i < NCPT; i++) sum += expf(sc[i] - mx);
            out[k*NCPT + c] = expf(v - mx) / sum;
        }
    }
}

// ---------------- launch ----------------
extern "C" void kernel_launch(void* const* d_in, const int* in_sizes, int n_in,
                              void* d_out, int out_size) {
    const float* X  = (const float*)d_in[0];
    const float* W1 = (const float*)d_in[1];
    const float* b1 = (const float*)d_in[2];
    const float* W2 = (const float*)d_in[3];
    const float* b2 = (const float*)d_in[4];
    const float* W3 = (const float*)d_in[5];
    const float* b3 = (const float*)d_in[6];
    const float* W4 = (const float*)d_in[7];
    const float* b4 = (const float*)d_in[8];
    const float* Wc = (const float*)d_in[9];
    const float* bc = (const float*)d_in[10];
    float* out = (float*)d_out;

    float *G, *q, *pooled, *t1, *t2; unsigned* trip; int* cnt;
    cudaGetSymbolAddress((void**)&G,      g_G);
    cudaGetSymbolAddress((void**)&trip,   g_trip);
    cudaGetSymbolAddress((void**)&cnt,    g_cnt);
    cudaGetSymbolAddress((void**)&q,      g_q);
    cudaGetSymbolAddress((void**)&pooled, g_pooled);
    cudaGetSymbolAddress((void**)&t1,     g_t1);
    cudaGetSymbolAddress((void**)&t2,     g_t2);

    const int smem1 = NEMB * DIM * sizeof(float);          // 51.2 KB (mask part)
    const int smem2 = 75*32*16 + 16*32*16;                 // 46.6 KB (mega)
    static int configured = 0;
    if (!configured) {
        cudaFuncSetAttribute(fused1_kernel, cudaFuncAttributeMaxDynamicSharedMemorySize, smem1);
        cudaFuncSetAttribute(mega_kernel,  cudaFuncAttributeMaxDynamicSharedMemorySize, smem2);
        configured = 1;
    }

    fused1_kernel<<<128, 256, smem1>>>(X, W1, G, trip, cnt);
    mega_kernel<<<NB2, 512, smem2>>>(G, b1, trip, cnt,
                                     W2, b2, W3, b3, W4, b4, Wc, bc,
                                     q, pooled, t1, t2, out);
}

// round 6
// speedup vs baseline: 3.0815x; 1.0570x over previous
#include <cuda_runtime.h>
#include <math.h>
#include <stdint.h>

#define NTASK 16
#define NEMB  25
#define DIM   512
#define HID   1024
#define NTRIP 2000
#define NCPT  64
#define M_ALL (NTASK*NEMB)   // 400
#define GCOLS (3*HID)        // 3072
#define NB2   128            // grid of mega kernel (<=148: one wave, barrier-safe)

// ---------------- scratch ----------------
__device__ float    g_G[M_ALL*GCOLS];
__device__ unsigned g_trip[NTASK*NTRIP];
__device__ int      g_cnt[NTASK];
__device__ float    g_q[NTASK*HID];
__device__ float    g_pooled[NTASK*DIM];
__device__ float    g_t1[NTASK*HID];
__device__ float    g_t2[NTASK*DIM];
__device__ unsigned g_bcnt[4];
__device__ unsigned g_bgen[4];

__device__ __forceinline__ float warp_sum(float v) {
    #pragma unroll
    for (int o = 16; o > 0; o >>= 1) v += __shfl_xor_sync(0xffffffffu, v, o);
    return v;
}

__device__ __forceinline__ uint32_t tf32r(float f) {
    uint32_t r;
    asm("cvt.rna.tf32.f32 %0, %1;" : "=r"(r) : "f"(f));
    return r;
}

__device__ __forceinline__ void grid_barrier(int s, unsigned nb) {
    __syncthreads();
    if (threadIdx.x == 0) {
        unsigned g0 = *((volatile unsigned*)&g_bgen[s]);
        __threadfence();
        unsigned old = atomicAdd(&g_bcnt[s], 1u);
        if (old == nb - 1u) {
            g_bcnt[s] = 0u;
            __threadfence();
            atomicAdd(&g_bgen[s], 1u);
        } else {
            while (*((volatile unsigned*)&g_bgen[s]) == g0) { }
            __threadfence();
        }
    }
    __syncthreads();
}

// ============================================================================
// L1: fused  [blocks 0..111] pipelined tf32 GEMM  |  [112..127] triplet mining
// ============================================================================
__global__ __launch_bounds__(256) void fused1_kernel(const float* __restrict__ X,
                                                     const float* __restrict__ W1,
                                                     float* __restrict__ G,
                                                     unsigned* __restrict__ trip,
                                                     int* __restrict__ cnt) {
    int bid = blockIdx.x;
    int tid = threadIdx.x;

    if (bid < 112) {
        // ---------- GEMM: BM=64, BN=192, BK=16, double-buffered ----------
        __shared__ uint32_t As[2][16][72];
        __shared__ uint32_t Bs[2][16][200];
        int m0 = (bid >> 4) * 64;
        int n0 = (bid & 15) * 192;
        int w = tid >> 5, lane = tid & 31;
        int wm = w & 1, wn = w >> 1;
        int grp = lane >> 2, tid4 = lane & 3;

        float c[2][6][4];
        #pragma unroll
        for (int mt = 0; mt < 2; mt++)
            #pragma unroll
            for (int nt = 0; nt < 6; nt++)
                #pragma unroll
                for (int r = 0; r < 4; r++) c[mt][nt][r] = 0.f;

        int lam = tid >> 2, lak = (tid & 3) << 2;
        int lbr = tid >> 4, lbc = (tid & 15) << 2;
        int gm = m0 + lam;
        bool arow_ok = (gm < M_ALL);

        const float* bptr[3];
        #pragma unroll
        for (int c3 = 0; c3 < 3; c3++) {
            int gc = n0 + lbc + c3*64;
            int s  = gc >> 10;
            int j  = gc & 1023;
            bptr[c3] = W1 + ((size_t)(s << 9)) * 1024 + j;
        }

        float4 ra;
        float4 rb[3];
        // prefetch tile 0
        {
            ra = arow_ok ? *reinterpret_cast<const float4*>(&X[(size_t)gm*DIM + lak])
                         : make_float4(0.f, 0.f, 0.f, 0.f);
            #pragma unroll
            for (int c3 = 0; c3 < 3; c3++)
                rb[c3] = *reinterpret_cast<const float4*>(bptr[c3] + (size_t)lbr * 1024);
        }
        // store tile 0 -> buf 0
        {
            As[0][lak+0][lam] = tf32r(ra.x);
            As[0][lak+1][lam] = tf32r(ra.y);
            As[0][lak+2][lam] = tf32r(ra.z);
            As[0][lak+3][lam] = tf32r(ra.w);
            #pragma unroll
            for (int c3 = 0; c3 < 3; c3++) {
                int bc = lbc + c3*64;
                Bs[0][lbr][bc+0] = tf32r(rb[c3].x);
                Bs[0][lbr][bc+1] = tf32r(rb[c3].y);
                Bs[0][lbr][bc+2] = tf32r(rb[c3].z);
                Bs[0][lbr][bc+3] = tf32r(rb[c3].w);
            }
        }
        __syncthreads();

        #pragma unroll 1
        for (int it = 0; it < 32; it++) {
            int cur = it & 1;
            // prefetch next tile into registers (hidden under mma)
            if (it < 31) {
                int k0 = (it + 1) * 16;
                ra = arow_ok ? *reinterpret_cast<const float4*>(&X[(size_t)gm*DIM + k0 + lak])
                             : make_float4(0.f, 0.f, 0.f, 0.f);
                #pragma unroll
                for (int c3 = 0; c3 < 3; c3++)
                    rb[c3] = *reinterpret_cast<const float4*>(bptr[c3] + (size_t)(k0 + lbr) * 1024);
            }
            // mma over current buffer
            #pragma unroll
            for (int ks = 0; ks < 16; ks += 8) {
                uint32_t a[2][4], b[6][2];
                #pragma unroll
                for (int mt = 0; mt < 2; mt++) {
                    int mr = wm*32 + mt*16 + grp;
                    a[mt][0] = As[cur][ks + tid4][mr];
                    a[mt][1] = As[cur][ks + tid4][mr + 8];
                    a[mt][2] = As[cur][ks + tid4 + 4][mr];
                    a[mt][3] = As[cur][ks + tid4 + 4][mr + 8];
                }
                #pragma unroll
                for (int nt = 0; nt < 6; nt++) {
                    int nc = wn*48 + nt*8 + grp;
                    b[nt][0] = Bs[cur][ks + tid4][nc];
                    b[nt][1] = Bs[cur][ks + tid4 + 4][nc];
                }
                #pragma unroll
                for (int mt = 0; mt < 2; mt++)
                    #pragma unroll
                    for (int nt = 0; nt < 6; nt++) {
                        asm volatile(
                            "mma.sync.aligned.m16n8k8.row.col.f32.tf32.tf32.f32 "
                            "{%0,%1,%2,%3}, {%4,%5,%6,%7}, {%8,%9}, {%0,%1,%2,%3};"
                            : "+f"(c[mt][nt][0]), "+f"(c[mt][nt][1]),
                              "+f"(c[mt][nt][2]), "+f"(c[mt][nt][3])
                            : "r"(a[mt][0]), "r"(a[mt][1]), "r"(a[mt][2]), "r"(a[mt][3]),
                              "r"(b[nt][0]), "r"(b[nt][1]));
                    }
            }
            // store prefetched tile into other buffer
            if (it < 31) {
                int nxt = cur ^ 1;
                As[nxt][lak+0][lam] = tf32r(ra.x);
                As[nxt][lak+1][lam] = tf32r(ra.y);
                As[nxt][lak+2][lam] = tf32r(ra.z);
                As[nxt][lak+3][lam] = tf32r(ra.w);
                #pragma unroll
                for (int c3 = 0; c3 < 3; c3++) {
                    int bc = lbc + c3*64;
                    Bs[nxt][lbr][bc+0] = tf32r(rb[c3].x);
                    Bs[nxt][lbr][bc+1] = tf32r(rb[c3].y);
                    Bs[nxt][lbr][bc+2] = tf32r(rb[c3].z);
                    Bs[nxt][lbr][bc+3] = tf32r(rb[c3].w);
                }
                __syncthreads();
            }
        }
        #pragma unroll
        for (int mt = 0; mt < 2; mt++) {
            int r0 = m0 + wm*32 + mt*16 + grp;
            int r1 = r0 + 8;
            #pragma unroll
            for (int nt = 0; nt < 6; nt++) {
                int col = n0 + wn*48 + nt*8 + 2*tid4;
                if (r0 < M_ALL) {
                    G[(size_t)r0*GCOLS + col]     = c[mt][nt][0];
                    G[(size_t)r0*GCOLS + col + 1] = c[mt][nt][1];
                }
                if (r1 < M_ALL) {
                    G[(size_t)r1*GCOLS + col]     = c[mt][nt][2];
                    G[(size_t)r1*GCOLS + col + 1] = c[mt][nt][3];
                }
            }
        }
    } else {
        // ------------------- mining part (task = bid - 112) -------------------
        extern __shared__ float xs[];    // 25*512 floats = 51.2 KB
        __shared__ float invn[NEMB], sqv[NEMB];
        __shared__ float D[NEMB][NEMB];
        __shared__ int wcnt[8];
        __shared__ int base_sh;
        int k = bid - 112;
        int wid = tid >> 5, lane = tid & 31;

        const float4* xb4 = reinterpret_cast<const float4*>(X + (size_t)k * NEMB * DIM);
        float4* xs4 = reinterpret_cast<float4*>(xs);
        for (int i = tid; i < NEMB * (DIM/4); i += 256) xs4[i] = xb4[i];
        __syncthreads();

        for (int r = wid; r < NEMB; r += 8) {
            float s = 0.f;
            for (int d = lane; d < DIM; d += 32) { float v = xs[r*DIM + d]; s += v*v; }
            s = warp_sum(s);
            if (lane == 0) invn[r] = rsqrtf(s);
        }
        __syncthreads();
        for (int i = tid; i < NEMB*DIM; i += 256) xs[i] *= invn[i >> 9];
        __syncthreads();
        for (int r = wid; r < NEMB; r += 8) {
            float s = 0.f;
            for (int d = lane; d < DIM; d += 32) { float v = xs[r*DIM + d]; s += v*v; }
            s = warp_sum(s);
            if (lane == 0) sqv[r] = s;
        }
        __syncthreads();
        for (int p = wid; p < 300; p += 8) {
            int i = 0, rem = p;
            while (rem >= 24 - i) { rem -= 24 - i; i++; }
            int j = i + 1 + rem;
            float s = 0.f;
            for (int cc = lane; cc < DIM/4; cc += 32) {
                float4 a = xs4[i*(DIM/4) + cc];
                float4 b = xs4[j*(DIM/4) + cc];
                s += a.x*b.x + a.y*b.y + a.z*b.z + a.w*b.w;
            }
            s = warp_sum(s);
            if (lane == 0) {
                float d2 = sqv[i] + sqv[j] - 2.f*s;
                float dd = sqrtf(fmaxf(d2, 0.f));
                D[i][j] = dd; D[j][i] = dd;
            }
        }
        __syncthreads();

        if (tid == 0) base_sh = 0;
        __syncthreads();
        for (int rnd = 0; rnd < 8; rnd++) {
            int t = rnd*256 + tid;
            bool f = false; unsigned pack = 0;
            if (t < NTRIP) {
                int a  = t / 80;
                int rm = t - a*80;
                int pi = rm / 20, ni = rm - (rm/20)*20;
                int lbl = a % 5, ga = a / 5;
                int pg = pi + (pi >= ga ? 1 : 0);
                int p  = lbl + 5*pg;
                int m  = ni >> 2, w = ni & 3;
                int wn = w + (w >= lbl ? 1 : 0);
                int n  = 5*m + wn;
                float tm = D[a][n] - D[a][p];
                f = (tm > 0.f && tm <= 0.8f);
                pack = (unsigned)(a | (p << 5) | (n << 10));
            }
            unsigned bal = __ballot_sync(0xffffffffu, f);
            if (lane == 0) wcnt[wid] = __popc(bal);
            __syncthreads();
            int off = base_sh;
            #pragma unroll
            for (int w8 = 0; w8 < 8; w8++) if (w8 < wid) off += wcnt[w8];
            off += __popc(bal & ((1u << lane) - 1u));
            if (f) trip[k*NTRIP + off] = pack;
            __syncthreads();
            if (tid == 0) {
                int s = 0;
                #pragma unroll
                for (int w8 = 0; w8 < 8; w8++) s += wcnt[w8];
                base_sh += s;
            }
            __syncthreads();
        }
        if (tid == 0) cnt[k] = base_sh;
    }
}

// ============================================================================
// L2: mega kernel — pool -> head1 -> head2 -> head3 -> final
// dyn smem: sG (38400) | regionB (8192: red / sf / fred+sc) | strip (8000)
// ============================================================================
__device__ __forceinline__ void head_stage(const float* __restrict__ in,
                                           const float* __restrict__ W,
                                           const float* __restrict__ bvec,
                                           const int* __restrict__ cntp,
                                           float* __restrict__ outp,
                                           int Nin, int Nout, int mode,
                                           int jb, int kb,
                                           float (*sf)[16], int tid) {
    int kb64 = kb * 64;
    for (int idx = tid; idx < 1024; idx += 512) {
        int il = idx >> 4, t = idx & 15;
        float v = in[t*Nin + kb64 + il];
        if (mode == 1)      v += (float)cntp[t] * bvec[kb64 + il];
        else if (mode == 2) v  = fmaxf(v + bvec[kb64 + il], 0.f);
        sf[il][t] = v;
    }
    __syncthreads();
    int j  = jb*64 + (tid & 63);
    int kh = tid >> 6;
    float acc[16];
    #pragma unroll
    for (int t = 0; t < 16; t++) acc[t] = 0.f;
    const float4* sf4 = reinterpret_cast<const float4*>(sf);
    #pragma unroll
    for (int ii = 0; ii < 8; ii++) {
        int i = (kh << 3) + ii;
        float wv = __ldg(&W[(size_t)(kb64 + i)*Nout + j]);
        float4 f0 = sf4[i*4 + 0];
        float4 f1 = sf4[i*4 + 1];
        float4 f2 = sf4[i*4 + 2];
        float4 f3 = sf4[i*4 + 3];
        acc[0]  += f0.x*wv; acc[1]  += f0.y*wv; acc[2]  += f0.z*wv; acc[3]  += f0.w*wv;
        acc[4]  += f1.x*wv; acc[5]  += f1.y*wv; acc[6]  += f1.z*wv; acc[7]  += f1.w*wv;
        acc[8]  += f2.x*wv; acc[9]  += f2.y*wv; acc[10] += f2.z*wv; acc[11] += f2.w*wv;
        acc[12] += f3.x*wv; acc[13] += f3.y*wv; acc[14] += f3.z*wv; acc[15] += f3.w*wv;
    }
    #pragma unroll
    for (int t = 0; t < 16; t++)
        atomicAdd(&outp[t*Nout + j], acc[t]);
}

__global__ __launch_bounds__(512) void mega_kernel(const float* __restrict__ G,
                                                   const float* __restrict__ b1,
                                                   const unsigned* __restrict__ trip,
                                                   const int* __restrict__ cnt,
                                                   const float* __restrict__ W2,
                                                   const float* __restrict__ b2,
                                                   const float* __restrict__ W3,
                                                   const float* __restrict__ b3,
                                                   const float* __restrict__ W4,
                                                   const float* __restrict__ b4v,
                                                   const float* __restrict__ Wc,
                                                   const float* __restrict__ bc,
                                                   float* __restrict__ q,
                                                   float* __restrict__ pooled,
                                                   float* __restrict__ t1,
                                                   float* __restrict__ t2,
                                                   float* __restrict__ out) {
    extern __shared__ char smem2[];
    float4 (*sG)[32]  = reinterpret_cast<float4(*)[32]>(smem2);          // 38400
    char* rb = smem2 + 75*32*16;
    float4 (*red)[32] = reinterpret_cast<float4(*)[32]>(rb);             // 8192 (pool)
    float  (*sf)[16]  = reinterpret_cast<float(*)[16]>(rb);              // 4096 (heads)
    float  (*fred)[64]= reinterpret_cast<float(*)[64]>(rb);              // 2048 (final)
    float*  sc        = reinterpret_cast<float*>(rb + 8*64*4);
    unsigned* strip   = reinterpret_cast<unsigned*>(rb + 8192);          // 8000

    int bid = blockIdx.x;
    int tid = threadIdx.x;
    unsigned nb = gridDim.x;

    // ---- zero atomic accumulators ----
    {
        int gidx = bid*512 + tid;
        if (gidx < NTASK*DIM)  pooled[gidx] = 0.f;
        if (gidx < NTASK*HID)  t1[gidx]     = 0.f;
        if (gidx < NTASK*DIM)  t2[gidx]     = 0.f;
    }

    // ---- stage 0: pool (block = (task k, col-chunk cb)) ----
    {
        int cb = bid & 7, k = bid >> 3;
        int w = tid >> 5, lane = tid & 31;
        const float* Gt = G + (size_t)k * NEMB * GCOLS;
        int n = cnt[k];
        for (int idx = tid; idx < 75*32; idx += 512) {
            int c = idx & 31, row = idx >> 5;
            int s = row / NEMB, i = row - s*NEMB;
            sG[row][c] = *reinterpret_cast<const float4*>(
                &Gt[(size_t)i*GCOLS + (s << 10) + (cb << 7) + (c << 2)]);
        }
        const unsigned* tp = trip + k*NTRIP;
        for (int i = tid; i < n; i += 512) strip[i] = __ldg(&tp[i]);
        __syncthreads();
        float4 b1v = *reinterpret_cast<const float4*>(&b1[(cb << 7) + (lane << 2)]);
        int lo = (w * n) >> 4;
        int hi = ((w + 1) * n) >> 4;
        float4 acc0 = make_float4(0.f, 0.f, 0.f, 0.f);
        float4 acc1 = make_float4(0.f, 0.f, 0.f, 0.f);
        int cur_a = -1, cur_p = -1;
        float4 fa = acc0, fap = acc0;
        int t = lo;
        for (; t + 1 < hi; t += 2) {
            unsigned u0 = strip[t], u1 = strip[t+1];
            int a0 = u0 & 31, p0 = (u0 >> 5) & 31, n0 = (u0 >> 10) & 31;
            int a1 = u1 & 31, p1 = (u1 >> 5) & 31, n1 = (u1 >> 10) & 31;
            if (a0 != cur_a) {
                float4 g = sG[a0][lane];
                fa.x = g.x + b1v.x; fa.y = g.y + b1v.y;
                fa.z = g.z + b1v.z; fa.w = g.w + b1v.w;
                cur_a = a0; cur_p = -1;
            }
            if (p0 != cur_p) {
                float4 g = sG[25 + p0][lane];
                fap.x = fa.x + g.x; fap.y = fa.y + g.y;
                fap.z = fa.z + g.z; fap.w = fa.w + g.w;
                cur_p = p0;
            }
            float4 gn0 = sG[50 + n0][lane];
            float4 fap0 = fap;
            if (a1 != cur_a) {
                float4 g = sG[a1][lane];
                fa.x = g.x + b1v.x; fa.y = g.y + b1v.y;
                fa.z = g.z + b1v.z; fa.w = g.w + b1v.w;
                cur_a = a1; cur_p = -1;
            }
            if (p1 != cur_p) {
                float4 g = sG[25 + p1][lane];
                fap.x = fa.x + g.x; fap.y = fa.y + g.y;
                fap.z = fa.z + g.z; fap.w = fa.w + g.w;
                cur_p = p1;
            }
            float4 gn1 = sG[50 + n1][lane];
            acc0.x += fmaxf(fap0.x + gn0.x, 0.f);
            acc0.y += fmaxf(fap0.y + gn0.y, 0.f);
            acc0.z += fmaxf(fap0.z + gn0.z, 0.f);
            acc0.w += fmaxf(fap0.w + gn0.w, 0.f);
            acc1.x += fmaxf(fap.x + gn1.x, 0.f);
            acc1.y += fmaxf(fap.y + gn1.y, 0.f);
            acc1.z += fmaxf(fap.z + gn1.z, 0.f);
            acc1.w += fmaxf(fap.w + gn1.w, 0.f);
        }
        if (t < hi) {
            unsigned u = strip[t];
            int a = u & 31, p = (u >> 5) & 31, nn = (u >> 10) & 31;
            if (a != cur_a) {
                float4 g = sG[a][lane];
                fa.x = g.x + b1v.x; fa.y = g.y + b1v.y;
                fa.z = g.z + b1v.z; fa.w = g.w + b1v.w;
                cur_a = a; cur_p = -1;
            }
            if (p != cur_p) {
                float4 g = sG[25 + p][lane];
                fap.x = fa.x + g.x; fap.y = fa.y + g.y;
                fap.z = fa.z + g.z; fap.w = fa.w + g.w;
                cur_p = p;
            }
            float4 gn = sG[50 + nn][lane];
            acc0.x += fmaxf(fap.x + gn.x, 0.f);
            acc0.y += fmaxf(fap.y + gn.y, 0.f);
            acc0.z += fmaxf(fap.z + gn.z, 0.f);
            acc0.w += fmaxf(fap.w + gn.w, 0.f);
        }
        acc0.x += acc1.x; acc0.y += acc1.y; acc0.z += acc1.z; acc0.w += acc1.w;
        red[w][lane] = acc0;
        __syncthreads();
        if (tid < 32) {
            float4 s = red[0][tid];
            #pragma unroll
            for (int g = 1; g < 16; g++) {
                float4 r = red[g][tid];
                s.x += r.x; s.y += r.y; s.z += r.z; s.w += r.w;
            }
            *reinterpret_cast<float4*>(&q[k*HID + (cb << 7) + (tid << 2)]) = s;
        }
    }
    grid_barrier(0, nb);

    head_stage(q, W2, nullptr, nullptr, pooled, HID, DIM, 0, bid & 7, bid >> 3, sf, tid);
    grid_barrier(1, nb);

    head_stage(pooled, W3, b2, cnt, t1, DIM, HID, 1, bid & 15, bid >> 4, sf, tid);
    grid_barrier(2, nb);

    head_stage(t1, W4, b3, nullptr, t2, HID, DIM, 2, bid & 7, bid >> 3, sf, tid);
    grid_barrier(3, nb);

    if (bid < NTASK) {
        int k = bid;
        int c = tid & 63, seg = tid >> 6;
        float acc = 0.f;
        const float* tk = t2 + k*DIM;
        for (int i = seg*64; i < seg*64 + 64; i++)
            acc += (tk[i] + b4v[i]) * Wc[i*NCPT + c];
        fred[seg][c] = acc;
        __syncthreads();
        if (tid < NCPT) {
            float s = bc[c];
            #pragma unroll
            for (int g = 0; g < 8; g++) s += fred[g][c];
            sc[c] = s;
        }
        __syncthreads();
        if (tid < NCPT) {
            float v = sc[c];
            float mx = -1e30f;
            #pragma unroll
            for (int i = 0; i < NCPT; i++) mx = fmaxf(mx, sc[i]);
            float sum = 0.f;
            #pragma unroll
            for (int i = 0; i < NCPT; i++) sum += expf(sc[i] - mx);
            out[k*NCPT + c] = expf(v - mx) / sum;
        }
    }
}

// ---------------- launch ----------------
extern "C" void kernel_launch(void* const* d_in, const int* in_sizes, int n_in,
                              void* d_out, int out_size) {
    const float* X  = (const float*)d_in[0];
    const float* W1 = (const float*)d_in[1];
    const float* b1 = (const float*)d_in[2];
    const float* W2 = (const float*)d_in[3];
    const float* b2 = (const float*)d_in[4];
    const float* W3 = (const float*)d_in[5];
    const float* b3 = (const float*)d_in[6];
    const float* W4 = (const float*)d_in[7];
    const float* b4 = (const float*)d_in[8];
    const float* Wc = (const float*)d_in[9];
    const float* bc = (const float*)d_in[10];
    float* out = (float*)d_out;

    float *G, *q, *pooled, *t1, *t2; unsigned* trip; int* cnt;
    cudaGetSymbolAddress((void**)&G,      g_G);
    cudaGetSymbolAddress((void**)&trip,   g_trip);
    cudaGetSymbolAddress((void**)&cnt,    g_cnt);
    cudaGetSymbolAddress((void**)&q,      g_q);
    cudaGetSymbolAddress((void**)&pooled, g_pooled);
    cudaGetSymbolAddress((void**)&t1,     g_t1);
    cudaGetSymbolAddress((void**)&t2,     g_t2);

    const int smem1 = NEMB * DIM * sizeof(float);          // 51.2 KB (mask part)
    const int smem2 = 75*32*16 + 16*32*16 + NTRIP*4;       // 54.6 KB (mega)
    static int configured = 0;
    if (!configured) {
        cudaFuncSetAttribute(fused1_kernel, cudaFuncAttributeMaxDynamicSharedMemorySize, smem1);
        cudaFuncSetAttribute(mega_kernel,  cudaFuncAttributeMaxDynamicSharedMemorySize, smem2);
        configured = 1;
    }

    fused1_kernel<<<128, 256, smem1>>>(X, W1, G, trip, cnt);
    mega_kernel<<<NB2, 512, smem2>>>(G, b1, trip, cnt,
                                     W2, b2, W3, b3, W4, b4, Wc, bc,
                                     q, pooled, t1, t2, out);
}